// round 9
// baseline (speedup 1.0000x reference)
#include <cuda_runtime.h>
#include <cstdint>

// Problem constants
#define RES    64
#define C_CH   8
#define NB     64
#define CORE   32
#define POS    16                        // (RES-CORE)/2
#define DIM    (CORE*CORE*CORE*C_CH)     // 262144
#define BATCH  32
#define VOL    (RES*RES*RES)             // 262144
#define BSTRIDE (C_CH*VOL)               // 2097152 floats per batch

#define TPB 256
#define BPB 8                            // batches per block
#define DPT 4                            // d-values per thread (one LDG.128 of U)
#define NBLOCKS ((DIM / (TPB * DPT)) * (BATCH / BPB))    // 256 stripes * 4 = 1024

// f4-unit strides
#define BSTRIDE4 (BSTRIDE / 4)           // 524288
#define VOL4     (VOL / 4)               // 65536

// Per block: 8 batches x (core slab edges 768 f4 + adopted full slab 1024 f4)
//          = 14336 zero f4  -> 56 per thread, 7 per GEMM chunk (8 chunks)
#define ZPT 56

// ---- packed fp32x2 helpers (sm_10x FFMA2) ----
__device__ __forceinline__ unsigned long long pack2(float lo, float hi) {
    unsigned long long r;
    asm("mov.b64 %0, {%1, %2};" : "=l"(r) : "f"(lo), "f"(hi));
    return r;
}
__device__ __forceinline__ unsigned long long fma2(unsigned long long a,
                                                   unsigned long long b,
                                                   unsigned long long c) {
    unsigned long long r;
    asm("fma.rn.f32x2 %0, %1, %2, %3;" : "=l"(r) : "l"(a), "l"(b), "l"(c));
    return r;
}
__device__ __forceinline__ unsigned long long add2(unsigned long long a,
                                                   unsigned long long b) {
    unsigned long long r;
    asm("add.rn.f32x2 %0, %1, %2;" : "=l"(r) : "l"(a), "l"(b), "l"(b));
    return r;
}

// Homogeneous fused kernel: every block computes its 1024-d x 8-batch core tile
// AND zeroes the matching periphery, with zero-stores interleaved into the GEMM
// mainloop so DRAM writes and FMA/load latency overlap inside each warp.
//
// Block (stripe, bg): stripe = bid>>2 -> (c = stripe>>5, i = stripe&31);
//                     bg = (bid&3)*8.
// Owns, per batch b in [bg, bg+8):
//   - core slab (b, c, i+16): computes the 32x32 core, zeroes j-edges (512 f4)
//     and k-edges (256 f4)
//   - adopted full-periphery slab (b, c, i') with i' = i<16 ? i : i+32 (1024 f4)
__global__ __launch_bounds__(TPB, 3)
void core_part_fused(const float* __restrict__ z,
                     const float* __restrict__ U,
                     const float* __restrict__ L,
                     const float* __restrict__ mu,
                     float* __restrict__ out) {
    const unsigned tid = threadIdx.x;
    const unsigned stripe = blockIdx.x >> 2;               // 0..255
    const unsigned bg     = (blockIdx.x & 3) * BPB;        // 0/8/16/24
    const unsigned cc = stripe >> 5;                       // channel 0..7
    const unsigned ii = stripe & 31;                       // core i 0..31
    const unsigned iful = (ii < 16) ? ii : ii + 32;        // adopted full slab i'

    float4* out4 = reinterpret_cast<float4*>(out);
    const float4 zz = make_float4(0.f, 0.f, 0.f, 0.f);

    // ---- stage pre-duplicated coefficients: a_s[n*8+bl] = {a,a} ----
    __shared__ __align__(16) float2 a_s[NB * BPB];         // 4 KB
    #pragma unroll
    for (unsigned idx = tid; idx < NB * BPB; idx += TPB) {
        unsigned n  = idx >> 3;
        unsigned bl = idx & 7;
        float a = L[n] * z[(bg + bl) * NB + n];
        a_s[idx] = make_float2(a, a);
    }
    __syncthreads();

    const unsigned du = stripe * TPB + tid;                // f4-index into U row

    unsigned long long acc0[BPB], acc1[BPB];               // per batch: d0d1, d2d3
    #pragma unroll
    for (int b = 0; b < BPB; b++) { acc0[b] = 0ull; acc1[b] = 0ull; }

    const float4* U4 = reinterpret_cast<const float4*>(U);
    const ulonglong2* a_v = reinterpret_cast<const ulonglong2*>(a_s);

    // zero-store cursor: flat index t = q*256 + tid over 14336 f4,
    // decomposed incrementally into (bat 0..7, r 0..1791)
    unsigned zbat = 0, zr = tid;

    #pragma unroll
    for (unsigned chunk = 0; chunk < 8; chunk++) {
        // ---- 7 periphery zero stores (independent; feed DRAM writes) ----
        #pragma unroll
        for (int zq = 0; zq < 7; zq++) {
            unsigned slabbase = (bg + zbat) * (unsigned)BSTRIDE4 + cc * (unsigned)VOL4;
            unsigned addr;
            if (zr < 1024) {
                // adopted full-periphery slab
                addr = slabbase + iful * 1024 + zr;
            } else {
                unsigned rr = zr - 1024;                   // 0..767, core slab edges
                unsigned cbase = slabbase + (ii + POS) * 1024;
                if (rr < 512) {
                    unsigned row = rr >> 4;                // 0..31
                    unsigned jj = (row < POS) ? row : row + CORE;
                    addr = cbase + jj * 16 + (rr & 15);
                } else {
                    unsigned t2 = rr - 512;                // 0..255
                    unsigned j2 = (t2 >> 3) + POS;
                    unsigned q2 = t2 & 7;
                    unsigned k4 = (q2 < 4) ? q2 : q2 + 8;
                    addr = cbase + j2 * 16 + k4;
                }
            }
            out4[addr] = zz;
            zr += TPB;
            if (zr >= 1792) { zr -= 1792; zbat++; }
        }

        // ---- 8 GEMM n-iterations ----
        #pragma unroll
        for (unsigned nn = 0; nn < 8; nn++) {
            unsigned n = chunk * 8 + nn;
            float4 uv = __ldg(&U4[n * (unsigned)(DIM / 4) + du]);
            unsigned long long u01 = pack2(uv.x, uv.y);
            unsigned long long u23 = pack2(uv.z, uv.w);
            #pragma unroll
            for (int q = 0; q < 4; q++) {                  // 2 batches per iter
                ulonglong2 av = a_v[n * 4 + q];            // broadcast LDS.128
                acc0[2*q+0] = fma2(u01, av.x, acc0[2*q+0]);
                acc1[2*q+0] = fma2(u23, av.x, acc1[2*q+0]);
                acc0[2*q+1] = fma2(u01, av.y, acc0[2*q+1]);
                acc1[2*q+1] = fma2(u23, av.y, acc1[2*q+1]);
            }
        }
    }

    // ---- epilogue: add mu, store core (STG.128, coalesced) ----
    const float4 mv = __ldg(&reinterpret_cast<const float4*>(mu)[du]);
    const unsigned long long m01 = pack2(mv.x, mv.y);
    const unsigned long long m23 = pack2(mv.z, mv.w);

    const unsigned d0 = du * DPT;
    const unsigned k = d0 & 31;                            // multiple of 4
    const unsigned j = (d0 >> 5) & 31;

    const unsigned base = cc * VOL
                        + (ii + POS) * (RES * RES)
                        + (j + POS) * RES
                        + (k + POS)
                        + bg * (unsigned)BSTRIDE;

    #pragma unroll
    for (int b = 0; b < BPB; b++) {
        unsigned long long r0, r1;
        asm("add.rn.f32x2 %0, %1, %2;" : "=l"(r0) : "l"(acc0[b]), "l"(m01));
        asm("add.rn.f32x2 %0, %1, %2;" : "=l"(r1) : "l"(acc1[b]), "l"(m23));
        *reinterpret_cast<ulonglong2*>(&out[base + (unsigned)b * BSTRIDE]) =
            make_ulonglong2(r0, r1);
    }
}

extern "C" void kernel_launch(void* const* d_in, const int* in_sizes, int n_in,
                              void* d_out, int out_size) {
    const float* z  = (const float*)d_in[0];   // (32, 64)
    const float* U  = (const float*)d_in[1];   // (64, 262144)
    const float* L  = (const float*)d_in[2];   // (64,)
    const float* mu = (const float*)d_in[3];   // (262144,)
    float* out = (float*)d_out;                // (32, 8, 64, 64, 64)

    core_part_fused<<<NBLOCKS, TPB>>>(z, U, L, mu, out);
}

// round 10
// speedup vs baseline: 1.0867x; 1.0867x over previous
#include <cuda_runtime.h>
#include <cstdint>

// Problem constants
#define RES    64
#define C_CH   8
#define NB     64
#define CORE   32
#define POS    16                        // (RES-CORE)/2
#define DIM    (CORE*CORE*CORE*C_CH)     // 262144
#define BATCH  32
#define VOL    (RES*RES*RES)             // 262144 floats per (b,c) volume
#define BSTRIDE (C_CH*VOL)               // 2097152 floats per batch
#define BSTRIDE4 (BSTRIDE/4)
#define VOL4     (VOL/4)
#define SLABF   (RES*RES)                // 4096 floats per i-slab

#define TPB 256
#define BPB 8                            // batches per block
#define DPT 4                            // d per thread (one LDG.128 of U)
#define NBLOCKS ((DIM/(TPB*DPT)) * (BATCH/BPB))   // 256 stripes * 4 = 1024

// ---- packed fp32x2 helpers (sm_10x FFMA2) ----
__device__ __forceinline__ unsigned long long pack2(float lo, float hi) {
    unsigned long long r;
    asm("mov.b64 %0, {%1, %2};" : "=l"(r) : "f"(lo), "f"(hi));
    return r;
}
__device__ __forceinline__ unsigned long long fma2(unsigned long long a,
                                                   unsigned long long b,
                                                   unsigned long long c) {
    unsigned long long r;
    asm("fma.rn.f32x2 %0, %1, %2, %3;" : "=l"(r) : "l"(a), "l"(b), "l"(c));
    return r;
}

// Fused kernel. Block (stripe = bid>>2 -> (c,i core slab), bg = (bid&3)*8):
//   * 48 cp.async.bulk stores (4 KB each, from an SMEM zero buffer) zero the
//     bulk periphery: per batch, the adopted full slab (16 KB) + the core
//     slab's j-edges (2 x 4 KB). Issued up front; TMA engine drains them
//     while the warps run the GEMM.
//   * ragged k-edges (64 B runs) are zeroed with STG.128 interleaved in the loop.
//   * GEMM: thread = 4 consecutive d x 8 batches, f32x2 accumulators,
//     2 LDS.128 + register splats per n.
__global__ __launch_bounds__(TPB, 3)
void core_part_fused(const float* __restrict__ z,
                     const float* __restrict__ U,
                     const float* __restrict__ L,
                     const float* __restrict__ mu,
                     float* __restrict__ out) {
    __shared__ __align__(16) float zbuf[1024];      // 4 KB of zeros (bulk-copy source)
    __shared__ __align__(16) float a_s[NB * BPB];   // 2 KB coefficients (non-duplicated)

    const unsigned tid = threadIdx.x;
    const unsigned stripe = blockIdx.x >> 2;        // 0..255 -> (c, i)
    const unsigned bg     = (blockIdx.x & 3) * BPB; // 0/8/16/24
    const unsigned cc = stripe >> 5;                // channel 0..7
    const unsigned ii = stripe & 31;                // core i 0..31
    const unsigned iful = (ii < 16) ? ii : ii + 32; // adopted full-periphery slab

    const float4 zz = make_float4(0.f, 0.f, 0.f, 0.f);
    float4* out4 = reinterpret_cast<float4*>(out);

    // ---- prologue: stage zeros + coefficients ----
    reinterpret_cast<float4*>(zbuf)[tid] = zz;      // 256 f4 = 4 KB
    #pragma unroll
    for (unsigned idx = tid; idx < NB * BPB; idx += TPB) {
        unsigned n  = idx >> 3;
        unsigned bl = idx & 7;
        a_s[idx] = L[n] * z[(bg + bl) * NB + n];
    }
    __syncthreads();

    // ---- issue 48 bulk zero-stores (4 KB each), then let them drain async ----
    if (tid < 48) {
        asm volatile("fence.proxy.async.shared::cta;" ::: "memory");
        const unsigned s = tid / 6;                 // batch slot 0..7
        const unsigned t = tid - s * 6;             // 0..5
        const unsigned b = bg + s;
        size_t foff;                                // float offset
        if (t < 4)      foff = (size_t)b * BSTRIDE + cc * VOL + iful * SLABF + t * 1024;
        else if (t == 4) foff = (size_t)b * BSTRIDE + cc * VOL + (ii + POS) * SLABF;
        else            foff = (size_t)b * BSTRIDE + cc * VOL + (ii + POS) * SLABF + 3072;
        unsigned zsm = (unsigned)__cvta_generic_to_shared(zbuf);
        asm volatile(
            "cp.async.bulk.global.shared::cta.bulk_group [%0], [%1], %2;"
            :: "l"(out + foff), "r"(zsm), "n"(4096) : "memory");
        asm volatile("cp.async.bulk.commit_group;" ::: "memory");
    }

    // ---- GEMM mainloop with interleaved k-edge zero stores ----
    const unsigned du = stripe * TPB + tid;         // f4-index into U row

    unsigned long long acc0[BPB], acc1[BPB];        // per batch: d0d1, d2d3
    #pragma unroll
    for (int b = 0; b < BPB; b++) { acc0[b] = 0ull; acc1[b] = 0ull; }

    const float4* U4 = reinterpret_cast<const float4*>(U);
    const float4* a4 = reinterpret_cast<const float4*>(a_s);  // 2 per n

    // k-edge geometry for this thread (same every chunk, batch varies)
    const unsigned erow = tid >> 3;                 // 0..31
    const unsigned eq   = tid & 7;
    const unsigned ek4  = (eq < 4) ? eq : eq + 8;   // f4 col 0-3 / 12-15
    const unsigned ebase = cc * (unsigned)VOL4 + (ii + POS) * 1024 + erow * 16 + ek4;

    #pragma unroll
    for (unsigned chunk = 0; chunk < 8; chunk++) {
        // one ragged k-edge zero store (batch bg+chunk)
        out4[(bg + chunk) * (unsigned)BSTRIDE4 + ebase] = zz;

        #pragma unroll
        for (unsigned nn = 0; nn < 8; nn++) {
            const unsigned n = chunk * 8 + nn;
            float4 uv = __ldg(&U4[n * (unsigned)(DIM / 4) + du]);
            unsigned long long u01 = pack2(uv.x, uv.y);
            unsigned long long u23 = pack2(uv.z, uv.w);
            float4 alo = a4[n * 2 + 0];             // coefficients, batches 0..3
            float4 ahi = a4[n * 2 + 1];             // batches 4..7
            unsigned long long ab;
            ab = pack2(alo.x, alo.x); acc0[0]=fma2(u01,ab,acc0[0]); acc1[0]=fma2(u23,ab,acc1[0]);
            ab = pack2(alo.y, alo.y); acc0[1]=fma2(u01,ab,acc0[1]); acc1[1]=fma2(u23,ab,acc1[1]);
            ab = pack2(alo.z, alo.z); acc0[2]=fma2(u01,ab,acc0[2]); acc1[2]=fma2(u23,ab,acc1[2]);
            ab = pack2(alo.w, alo.w); acc0[3]=fma2(u01,ab,acc0[3]); acc1[3]=fma2(u23,ab,acc1[3]);
            ab = pack2(ahi.x, ahi.x); acc0[4]=fma2(u01,ab,acc0[4]); acc1[4]=fma2(u23,ab,acc1[4]);
            ab = pack2(ahi.y, ahi.y); acc0[5]=fma2(u01,ab,acc0[5]); acc1[5]=fma2(u23,ab,acc1[5]);
            ab = pack2(ahi.z, ahi.z); acc0[6]=fma2(u01,ab,acc0[6]); acc1[6]=fma2(u23,ab,acc1[6]);
            ab = pack2(ahi.w, ahi.w); acc0[7]=fma2(u01,ab,acc0[7]); acc1[7]=fma2(u23,ab,acc1[7]);
        }
    }

    // ---- epilogue: add mu, store core (STG.128, coalesced) ----
    const float4 mv = __ldg(&reinterpret_cast<const float4*>(mu)[du]);
    const unsigned long long m01 = pack2(mv.x, mv.y);
    const unsigned long long m23 = pack2(mv.z, mv.w);

    const unsigned d0 = du * DPT;
    const unsigned k = d0 & 31;                     // multiple of 4
    const unsigned j = (d0 >> 5) & 31;

    const unsigned base = cc * VOL
                        + (ii + POS) * (RES * RES)
                        + (j + POS) * RES
                        + (k + POS)
                        + bg * (unsigned)BSTRIDE;

    #pragma unroll
    for (int b = 0; b < BPB; b++) {
        unsigned long long r0, r1;
        asm("add.rn.f32x2 %0, %1, %2;" : "=l"(r0) : "l"(acc0[b]), "l"(m01));
        asm("add.rn.f32x2 %0, %1, %2;" : "=l"(r1) : "l"(acc1[b]), "l"(m23));
        *reinterpret_cast<ulonglong2*>(&out[base + (unsigned)b * BSTRIDE]) =
            make_ulonglong2(r0, r1);
    }

    // ---- ensure bulk zero-stores completed before block exit ----
    if (tid < 48) {
        asm volatile("cp.async.bulk.wait_group 0;" ::: "memory");
    }
}

extern "C" void kernel_launch(void* const* d_in, const int* in_sizes, int n_in,
                              void* d_out, int out_size) {
    const float* z  = (const float*)d_in[0];   // (32, 64)
    const float* U  = (const float*)d_in[1];   // (64, 262144)
    const float* L  = (const float*)d_in[2];   // (64,)
    const float* mu = (const float*)d_in[3];   // (262144,)
    float* out = (float*)d_out;                // (32, 8, 64, 64, 64)

    core_part_fused<<<NBLOCKS, TPB>>>(z, U, L, mu, out);
}

// round 11
// speedup vs baseline: 1.1427x; 1.0516x over previous
#include <cuda_runtime.h>
#include <cstdint>

// Problem constants
#define RES    64
#define C_CH   8
#define NB     64
#define CORE   32
#define POS    16                        // (RES-CORE)/2
#define DIM    (CORE*CORE*CORE*C_CH)     // 262144
#define BATCH  32
#define VOL    (RES*RES*RES)             // 262144 floats per (b,c) volume
#define BSTRIDE (C_CH*VOL)               // 2097152 floats per batch
#define BSTRIDE4 (BSTRIDE/4)
#define VOL4     (VOL/4)
#define SLABF   (RES*RES)                // 4096 floats per i-slab

#define TPB 256
#define BPB 8                            // batches per block
#define DPT 4                            // d per thread (one LDG.128 of U)
#define NBLOCKS ((DIM/(TPB*DPT)) * (BATCH/BPB))   // 256 stripes * 4 = 1024

// ---- packed fp32x2 helpers (sm_10x FFMA2) ----
__device__ __forceinline__ unsigned long long pack2(float lo, float hi) {
    unsigned long long r;
    asm("mov.b64 %0, {%1, %2};" : "=l"(r) : "f"(lo), "f"(hi));
    return r;
}
__device__ __forceinline__ unsigned long long fma2(unsigned long long a,
                                                   unsigned long long b,
                                                   unsigned long long c) {
    unsigned long long r;
    asm("fma.rn.f32x2 %0, %1, %2, %3;" : "=l"(r) : "l"(a), "l"(b), "l"(c));
    return r;
}

// Fused kernel. Block (stripe = bid>>2 -> (c,i core slab), bg = (bid&3)*8):
//   * periphery zeroed via cp.async.bulk (4 KB each from SMEM zero buffer),
//     6 ops (one batch's worth = 24 KB) issued at the TOP OF EACH GEMM CHUNK
//     so the async write stream is continuous over the block's lifetime
//     (R9 issued all 48 up front -> bursty writes -> DRAM pipe half idle).
//   * ragged k-edges (64 B runs) zeroed with one STG.128/thread/chunk.
//   * GEMM: thread = 4 consecutive d x 8 batches, f32x2 accumulators,
//     2 LDS.128 + register splats per n.
__global__ __launch_bounds__(TPB, 3)
void core_part_fused(const float* __restrict__ z,
                     const float* __restrict__ U,
                     const float* __restrict__ L,
                     const float* __restrict__ mu,
                     float* __restrict__ out) {
    __shared__ __align__(16) float zbuf[1024];      // 4 KB of zeros (bulk-copy source)
    __shared__ __align__(16) float a_s[NB * BPB];   // 2 KB coefficients

    const unsigned tid = threadIdx.x;
    const unsigned stripe = blockIdx.x >> 2;        // 0..255 -> (c, i)
    const unsigned bg     = (blockIdx.x & 3) * BPB; // 0/8/16/24
    const unsigned cc = stripe >> 5;                // channel 0..7
    const unsigned ii = stripe & 31;                // core i 0..31
    const unsigned iful = (ii < 16) ? ii : ii + 32; // adopted full-periphery slab

    const float4 zz = make_float4(0.f, 0.f, 0.f, 0.f);
    float4* out4 = reinterpret_cast<float4*>(out);

    // ---- prologue: stage zeros + coefficients ----
    reinterpret_cast<float4*>(zbuf)[tid] = zz;      // 256 f4 = 4 KB
    #pragma unroll
    for (unsigned idx = tid; idx < NB * BPB; idx += TPB) {
        unsigned n  = idx >> 3;
        unsigned bl = idx & 7;
        a_s[idx] = L[n] * z[(bg + bl) * NB + n];
    }
    __syncthreads();

    // Per-thread TMA role: threads 0..5 each own one 4 KB periphery piece per batch.
    const unsigned zsm = (unsigned)__cvta_generic_to_shared(zbuf);
    size_t tma_off = 0;                             // float offset for this thread's piece
    const bool tma_thread = (tid < 6);
    if (tma_thread) {
        if (tid < 4)       tma_off = (size_t)cc * VOL + iful * SLABF + tid * 1024;
        else if (tid == 4) tma_off = (size_t)cc * VOL + (ii + POS) * SLABF;
        else               tma_off = (size_t)cc * VOL + (ii + POS) * SLABF + 3072;
        asm volatile("fence.proxy.async.shared::cta;" ::: "memory");
    }

    // ---- GEMM mainloop; each chunk zeroes one batch's periphery ----
    const unsigned du = stripe * TPB + tid;         // f4-index into U row

    unsigned long long acc0[BPB], acc1[BPB];        // per batch: d0d1, d2d3
    #pragma unroll
    for (int b = 0; b < BPB; b++) { acc0[b] = 0ull; acc1[b] = 0ull; }

    const float4* U4 = reinterpret_cast<const float4*>(U);
    const float4* a4 = reinterpret_cast<const float4*>(a_s);  // 2 per n

    // k-edge geometry for this thread (same every chunk, batch varies)
    const unsigned erow = tid >> 3;                 // 0..31
    const unsigned eq   = tid & 7;
    const unsigned ek4  = (eq < 4) ? eq : eq + 8;   // f4 col 0-3 / 12-15
    const unsigned ebase = cc * (unsigned)VOL4 + (ii + POS) * 1024 + erow * 16 + ek4;

    #pragma unroll
    for (unsigned chunk = 0; chunk < 8; chunk++) {
        const unsigned bat = bg + chunk;

        // 6 bulk zero-stores for batch `bat` (async; drains during this chunk)
        if (tma_thread) {
            asm volatile(
                "cp.async.bulk.global.shared::cta.bulk_group [%0], [%1], %2;\n\t"
                "cp.async.bulk.commit_group;"
                :: "l"(out + (size_t)bat * BSTRIDE + tma_off), "r"(zsm), "n"(4096)
                : "memory");
        }

        // one ragged k-edge zero store (batch bat)
        out4[bat * (unsigned)BSTRIDE4 + ebase] = zz;

        #pragma unroll
        for (unsigned nn = 0; nn < 8; nn++) {
            const unsigned n = chunk * 8 + nn;
            float4 uv = __ldg(&U4[n * (unsigned)(DIM / 4) + du]);
            unsigned long long u01 = pack2(uv.x, uv.y);
            unsigned long long u23 = pack2(uv.z, uv.w);
            float4 alo = a4[n * 2 + 0];             // coefficients, batches 0..3
            float4 ahi = a4[n * 2 + 1];             // batches 4..7
            unsigned long long ab;
            ab = pack2(alo.x, alo.x); acc0[0]=fma2(u01,ab,acc0[0]); acc1[0]=fma2(u23,ab,acc1[0]);
            ab = pack2(alo.y, alo.y); acc0[1]=fma2(u01,ab,acc0[1]); acc1[1]=fma2(u23,ab,acc1[1]);
            ab = pack2(alo.z, alo.z); acc0[2]=fma2(u01,ab,acc0[2]); acc1[2]=fma2(u23,ab,acc1[2]);
            ab = pack2(alo.w, alo.w); acc0[3]=fma2(u01,ab,acc0[3]); acc1[3]=fma2(u23,ab,acc1[3]);
            ab = pack2(ahi.x, ahi.x); acc0[4]=fma2(u01,ab,acc0[4]); acc1[4]=fma2(u23,ab,acc1[4]);
            ab = pack2(ahi.y, ahi.y); acc0[5]=fma2(u01,ab,acc0[5]); acc1[5]=fma2(u23,ab,acc1[5]);
            ab = pack2(ahi.z, ahi.z); acc0[6]=fma2(u01,ab,acc0[6]); acc1[6]=fma2(u23,ab,acc1[6]);
            ab = pack2(ahi.w, ahi.w); acc0[7]=fma2(u01,ab,acc0[7]); acc1[7]=fma2(u23,ab,acc1[7]);
        }
    }

    // ---- epilogue: add mu, store core (STG.128, coalesced) ----
    const float4 mv = __ldg(&reinterpret_cast<const float4*>(mu)[du]);
    const unsigned long long m01 = pack2(mv.x, mv.y);
    const unsigned long long m23 = pack2(mv.z, mv.w);

    const unsigned d0 = du * DPT;
    const unsigned k = d0 & 31;                     // multiple of 4
    const unsigned j = (d0 >> 5) & 31;

    const unsigned base = cc * VOL
                        + (ii + POS) * (RES * RES)
                        + (j + POS) * RES
                        + (k + POS)
                        + bg * (unsigned)BSTRIDE;

    #pragma unroll
    for (int b = 0; b < BPB; b++) {
        unsigned long long r0, r1;
        asm("add.rn.f32x2 %0, %1, %2;" : "=l"(r0) : "l"(acc0[b]), "l"(m01));
        asm("add.rn.f32x2 %0, %1, %2;" : "=l"(r1) : "l"(acc1[b]), "l"(m23));
        *reinterpret_cast<ulonglong2*>(&out[base + (unsigned)b * BSTRIDE]) =
            make_ulonglong2(r0, r1);
    }

    // ---- ensure bulk zero-stores completed before block exit ----
    if (tma_thread) {
        asm volatile("cp.async.bulk.wait_group 0;" ::: "memory");
    }
}

extern "C" void kernel_launch(void* const* d_in, const int* in_sizes, int n_in,
                              void* d_out, int out_size) {
    const float* z  = (const float*)d_in[0];   // (32, 64)
    const float* U  = (const float*)d_in[1];   // (64, 262144)
    const float* L  = (const float*)d_in[2];   // (64,)
    const float* mu = (const float*)d_in[3];   // (262144,)
    float* out = (float*)d_out;                // (32, 8, 64, 64, 64)

    core_part_fused<<<NBLOCKS, TPB>>>(z, U, L, mu, out);
}